// round 9
// baseline (speedup 1.0000x reference)
#include <cuda_runtime.h>
#include <cuda_bf16.h>
#include <cstdint>

#define BB 4
#define CC 256
#define HH 256
#define WW 256
#define NROI_MAX 2048
#define FDIM 2304
#define DD 256

typedef __nv_bfloat16 bf16;
typedef __nv_bfloat162 bf162;

// ---------------- scratch ----------------------------------------------------
__device__ float g_fmt[BB * HH * WW * CC];

__device__ bf16 g_xhi[NROI_MAX * FDIM];
__device__ bf16 g_xlo[NROI_MAX * FDIM];

__device__ bf16 g_w1hi[DD * FDIM], g_w1lo[DD * FDIM];
__device__ bf16 g_w2hi[DD * DD],   g_w2lo[DD * DD];
__device__ bf16 g_wc1hi[DD * DD],  g_wc1lo[DD * DD];
__device__ bf16 g_wi1hi[DD * DD],  g_wi1lo[DD * DD];
__device__ bf16 g_wr1hi[DD * DD],  g_wr1lo[DD * DD];
__device__ bf16 g_wc2hi[DD * DD],  g_wc2lo[DD * DD];
__device__ bf16 g_wi2hi[DD * DD],  g_wi2lo[DD * DD];
__device__ bf16 g_wr2hi[DD * DD],  g_wr2lo[DD * DD];

__device__ float g_p0[NROI_MAX * DD];
__device__ float g_p1[NROI_MAX * DD];
__device__ float g_p2[NROI_MAX * DD];
__device__ float g_p3[NROI_MAX * DD];

__device__ bf16 g_h1hi[NROI_MAX * DD],  g_h1lo[NROI_MAX * DD];
__device__ bf16 g_shhi[NROI_MAX * DD],  g_shlo[NROI_MAX * DD];
__device__ bf16 g_t1chi[NROI_MAX * DD], g_t1clo[NROI_MAX * DD];
__device__ bf16 g_t1ihi[NROI_MAX * DD], g_t1ilo[NROI_MAX * DD];
__device__ bf16 g_t1rhi[NROI_MAX * DD], g_t1rlo[NROI_MAX * DD];
__device__ bf16 g_c2hi[NROI_MAX * DD],  g_c2lo[NROI_MAX * DD];
__device__ bf16 g_i2hi[NROI_MAX * DD],  g_i2lo[NROI_MAX * DD];
__device__ bf16 g_r2hi[NROI_MAX * DD],  g_r2lo[NROI_MAX * DD];

__device__ __forceinline__ void split_bf16(float f, bf16& h, bf16& l)
{
    h = __float2bfloat16(f);
    l = __float2bfloat16(f - __bfloat162float(h));
}

// ---------------- NCHW -> NHWC transpose (64c x 128s per block) -------------
__global__ __launch_bounds__(256)
void transpose_kernel(const float* __restrict__ fm, float* __restrict__ fmt)
{
    __shared__ float tile[64][129];

    const int b  = blockIdx.z;
    const int s0 = blockIdx.x * 128;
    const int c0 = blockIdx.y * 64;
    const int t  = threadIdx.x;

#pragma unroll
    for (int l = 0; l < 8; l++) {
        const int slot = t + l * 256;
        const int ci = slot >> 5;          // 0..63
        const int s4 = (slot & 31) * 4;    // 0..124
        const float4 v = *(const float4*)(fm +
            ((size_t)b * CC + (c0 + ci)) * (size_t)(HH * WW) + s0 + s4);
        tile[ci][s4 + 0] = v.x;
        tile[ci][s4 + 1] = v.y;
        tile[ci][s4 + 2] = v.z;
        tile[ci][s4 + 3] = v.w;
    }
    __syncthreads();

#pragma unroll
    for (int l = 0; l < 8; l++) {
        const int slot = t + l * 256;
        const int si = slot >> 4;          // 0..127
        const int c4 = (slot & 15) * 4;    // 0..60
        float4 v;
        v.x = tile[c4 + 0][si];
        v.y = tile[c4 + 1][si];
        v.z = tile[c4 + 2][si];
        v.w = tile[c4 + 3][si];
        *(float4*)(fmt + ((size_t)b * (HH * WW) + s0 + si) * (size_t)CC + c0 + c4) = v;
    }
}

// ---------------- RoIAlignRotated (NHWC gather, writes hi/lo bf16) ----------
__global__ __launch_bounds__(64)
void roi_kernel(const float* __restrict__ fmt,
                const float* __restrict__ boxes,
                const int*   __restrict__ bidx,
                bf16* __restrict__ xhi, bf16* __restrict__ xlo)
{
    const int n = blockIdx.x;
    const int t = threadIdx.x;

    __shared__ int   s_o[36][4];
    __shared__ float s_w[36][4];

    if (t < 36) {
        const float gw = (float)(102.4 / 256.0);
        const float bx  = boxes[n*7 + 0];
        const float by  = boxes[n*7 + 1];
        const float rh  = boxes[n*7 + 4] / gw;
        const float rw  = boxes[n*7 + 5] / gw;
        const float ang = boxes[n*7 + 6];

        const float cx = (bx + 51.2f) / gw - 0.5f;
        const float cy = (by + 51.2f) / gw - 0.5f;
        const float ct = cosf(-ang);
        const float st = sinf(-ang);
        const float bin_h = rh / 3.0f;
        const float bin_w = rw / 3.0f;

        const int p  = t;
        const int ph = p / 12;
        const int pw = (p / 4) % 3;
        const int sy = (p >> 1) & 1;
        const int sx = p & 1;

        const float yy = -rh * 0.5f + ((float)ph + ((float)sy + 0.5f) * 0.5f) * bin_h;
        const float xx = -rw * 0.5f + ((float)pw + ((float)sx + 0.5f) * 0.5f) * bin_w;

        float y = yy * ct - xx * st + cy;
        float x = yy * st + xx * ct + cx;

        const bool valid = (y > -1.0f) && (y < (float)HH) && (x > -1.0f) && (x < (float)WW);

        y = fminf(fmaxf(y, 0.0f), (float)(HH - 1));
        x = fminf(fmaxf(x, 0.0f), (float)(WW - 1));

        int y0 = min((int)floorf(y), HH - 1);
        int x0 = min((int)floorf(x), WW - 1);
        int y1 = min(y0 + 1, HH - 1);
        int x1 = min(x0 + 1, WW - 1);

        const float ly = y - (float)y0;
        const float lx = x - (float)x0;
        const float hy = 1.0f - ly;
        const float hx = 1.0f - lx;
        const float v  = valid ? 1.0f : 0.0f;

        s_o[p][0] = (y0 * WW + x0) * CC;
        s_o[p][1] = (y0 * WW + x1) * CC;
        s_o[p][2] = (y1 * WW + x0) * CC;
        s_o[p][3] = (y1 * WW + x1) * CC;
        s_w[p][0] = hy * hx * v;
        s_w[p][1] = hy * lx * v;
        s_w[p][2] = ly * hx * v;
        s_w[p][3] = ly * lx * v;
    }
    __syncthreads();

    const int b = bidx[n];
    const float* __restrict__ base = fmt + (size_t)b * (HH * WW) * CC + t * 4;

    float4 acc[9];
#pragma unroll
    for (int i = 0; i < 9; i++) acc[i] = make_float4(0.f, 0.f, 0.f, 0.f);

#pragma unroll
    for (int p = 0; p < 36; p++) {
        const float4 v0 = *(const float4*)(base + s_o[p][0]);
        const float4 v1 = *(const float4*)(base + s_o[p][1]);
        const float4 v2 = *(const float4*)(base + s_o[p][2]);
        const float4 v3 = *(const float4*)(base + s_o[p][3]);
        const float w0 = s_w[p][0], w1 = s_w[p][1], w2 = s_w[p][2], w3 = s_w[p][3];
        float4& a = acc[p >> 2];
        a.x += w0 * v0.x + w1 * v1.x + w2 * v2.x + w3 * v3.x;
        a.y += w0 * v0.y + w1 * v1.y + w2 * v2.y + w3 * v3.y;
        a.z += w0 * v0.z + w1 * v1.z + w2 * v2.z + w3 * v3.z;
        a.w += w0 * v0.w + w1 * v1.w + w2 * v2.w + w3 * v3.w;
    }

    const size_t ob = (size_t)n * FDIM + t * 4;
#pragma unroll
    for (int i = 0; i < 9; i++) {
        float r[4] = {acc[i].x * 0.25f, acc[i].y * 0.25f,
                      acc[i].z * 0.25f, acc[i].w * 0.25f};
        bf16 h[4], l[4];
#pragma unroll
        for (int j = 0; j < 4; j++) split_bf16(r[j], h[j], l[j]);
        *(bf162*)(xhi + ob + i * CC)     = bf162(h[0], h[1]);
        *(bf162*)(xhi + ob + i * CC + 2) = bf162(h[2], h[3]);
        *(bf162*)(xlo + ob + i * CC)     = bf162(l[0], l[1]);
        *(bf162*)(xlo + ob + i * CC + 2) = bf162(l[2], l[3]);
    }
}

// ---------------- merged weight split ---------------------------------------
__global__ __launch_bounds__(256)
void wsplit_all(const float* __restrict__ w1,
                const float* __restrict__ s0w, const float* __restrict__ s1w,
                const float* __restrict__ s2w, const float* __restrict__ s3w,
                const float* __restrict__ s4w, const float* __restrict__ s5w,
                const float* __restrict__ s6w,
                bf16* __restrict__ w1h, bf16* __restrict__ w1l,
                bf16* __restrict__ s0h, bf16* __restrict__ s0l,
                bf16* __restrict__ s1h, bf16* __restrict__ s1l,
                bf16* __restrict__ s2h, bf16* __restrict__ s2l,
                bf16* __restrict__ s3h, bf16* __restrict__ s3l,
                bf16* __restrict__ s4h, bf16* __restrict__ s4l,
                bf16* __restrict__ s5h, bf16* __restrict__ s5l,
                bf16* __restrict__ s6h, bf16* __restrict__ s6l)
{
    const int idx4 = (blockIdx.x * 256 + threadIdx.x) * 4;
    const int W1N = DD * FDIM;

    const float* w; bf16* h; bf16* l; int off;
    if (idx4 < W1N) {
        w = w1; h = w1h; l = w1l; off = idx4;
    } else {
        const int r = idx4 - W1N;
        const int seg = r >> 16;
        off = r & 65535;
        w = (seg == 0) ? s0w : (seg == 1) ? s1w : (seg == 2) ? s2w :
            (seg == 3) ? s3w : (seg == 4) ? s4w : (seg == 5) ? s5w : s6w;
        h = (seg == 0) ? s0h : (seg == 1) ? s1h : (seg == 2) ? s2h :
            (seg == 3) ? s3h : (seg == 4) ? s4h : (seg == 5) ? s5h : s6h;
        l = (seg == 0) ? s0l : (seg == 1) ? s1l : (seg == 2) ? s2l :
            (seg == 3) ? s3l : (seg == 4) ? s4l : (seg == 5) ? s5l : s6l;
    }

    const float4 v = *(const float4*)(w + off);
    bf16 h0, l0, h1, l1, h2, l2, h3, l3;
    split_bf16(v.x, h0, l0); split_bf16(v.y, h1, l1);
    split_bf16(v.z, h2, l2); split_bf16(v.w, h3, l3);
    *(bf162*)(h + off)     = bf162(h0, h1);
    *(bf162*)(h + off + 2) = bf162(h2, h3);
    *(bf162*)(l + off)     = bf162(l0, l1);
    *(bf162*)(l + off + 2) = bf162(l2, l3);
}

// ---------------- combine split-K partials: relu(sum Pi) -> hi/lo -----------
__global__ __launch_bounds__(256)
void combine_relu_split(const float* __restrict__ P0, const float* __restrict__ P1,
                        const float* __restrict__ P2, const float* __restrict__ P3,
                        bf16* __restrict__ Oh, bf16* __restrict__ Ol, int four)
{
    const int off = (blockIdx.x * 256 + threadIdx.x) * 4;
    const float4 a = *(const float4*)(P0 + off);
    const float4 b = *(const float4*)(P1 + off);
    float r[4] = {a.x + b.x, a.y + b.y, a.z + b.z, a.w + b.w};
    if (four) {
        const float4 c = *(const float4*)(P2 + off);
        const float4 d = *(const float4*)(P3 + off);
        r[0] += c.x + d.x; r[1] += c.y + d.y;
        r[2] += c.z + d.z; r[3] += c.w + d.w;
    }
    bf16 h[4], l[4];
#pragma unroll
    for (int j = 0; j < 4; j++) {
        r[j] = fmaxf(r[j], 0.0f);
        split_bf16(r[j], h[j], l[j]);
    }
    *(bf162*)(Oh + off)     = bf162(h[0], h[1]);
    *(bf162*)(Oh + off + 2) = bf162(h[2], h[3]);
    *(bf162*)(Ol + off)     = bf162(l[0], l[1]);
    *(bf162*)(Ol + off + 2) = bf162(l[2], l[3]);
}

// ---------------- GEMM common ------------------------------------------------
__device__ __forceinline__ void mma_bf16(float* d, const uint32_t* a, const uint32_t* b)
{
    asm volatile(
        "mma.sync.aligned.m16n8k16.row.col.f32.bf16.bf16.f32 "
        "{%0,%1,%2,%3}, {%4,%5,%6,%7}, {%8,%9}, {%0,%1,%2,%3};\n"
        : "+f"(d[0]), "+f"(d[1]), "+f"(d[2]), "+f"(d[3])
        : "r"(a[0]), "r"(a[1]), "r"(a[2]), "r"(a[3]), "r"(b[0]), "r"(b[1]));
}

__device__ __forceinline__ void cp_async16(uint32_t smem_addr, const void* gptr)
{
    asm volatile("cp.async.cg.shared.global [%0], [%1], 16;\n"
                 :: "r"(smem_addr), "l"(gptr));
}

#define LDSM4(r, addr) \
    asm volatile("ldmatrix.sync.aligned.m8n8.x4.shared.b16 {%0,%1,%2,%3}, [%4];" \
                 : "=r"((r)[0]), "=r"((r)[1]), "=r"((r)[2]), "=r"((r)[3]) \
                 : "r"(addr))

#define SKB 40
#define BUFE (64 * SKB)
#define BUFB (BUFE * 2)
#define SMEM_GEMM (4 * 2 * BUFE * 2)   // 40960 B

struct GemmCtx {
    uint32_t aHiB, aLoB, bHiB, bLoB, ldOff, aOff, bOff, P16;
    int lrow, ck;
};

__device__ __forceinline__ void gemm_mainloop(
    const bf16* __restrict__ Ah, const bf16* __restrict__ Al,
    const bf16* __restrict__ Bh, const bf16* __restrict__ Bl,
    int m0, int n0, int K, int kbase, int T,
    const GemmCtx& cx, float acc[3][4][4])
{
    const int lrow = cx.lrow, ck = cx.ck;
    {
        const size_t ka = (size_t)(m0 + lrow) * K + kbase + ck;
        const size_t kb = (size_t)(n0 + lrow) * K + kbase + ck;
        cp_async16(cx.aHiB + cx.ldOff, Ah + ka);
        cp_async16(cx.aLoB + cx.ldOff, Al + ka);
        cp_async16(cx.bHiB + cx.ldOff, Bh + kb);
        cp_async16(cx.bLoB + cx.ldOff, Bl + kb);
        asm volatile("cp.async.commit_group;\n");
    }

    for (int kt = 0; kt < T; kt++) {
        const uint32_t buf = (uint32_t)(kt & 1) * BUFB;
        if (kt + 1 < T) {
            const uint32_t nb = (uint32_t)((kt + 1) & 1) * BUFB;
            const int ko = kbase + ((kt + 1) << 5);
            const size_t ka = (size_t)(m0 + lrow) * K + ko + ck;
            const size_t kb = (size_t)(n0 + lrow) * K + ko + ck;
            cp_async16(cx.aHiB + nb + cx.ldOff, Ah + ka);
            cp_async16(cx.aLoB + nb + cx.ldOff, Al + ka);
            cp_async16(cx.bHiB + nb + cx.ldOff, Bh + kb);
            cp_async16(cx.bLoB + nb + cx.ldOff, Bl + kb);
            asm volatile("cp.async.commit_group;\n");
            asm volatile("cp.async.wait_group 1;\n");
        } else {
            asm volatile("cp.async.wait_group 0;\n");
        }
        __syncthreads();

#pragma unroll
        for (int ks = 0; ks < 32; ks += 16) {
            const uint32_t d = buf + (uint32_t)ks * 2;
            uint32_t ah[4], al[4], b0h[4], b1h[4], b0l[4], b1l[4];
            LDSM4(ah,  cx.aHiB + cx.aOff + d);
            LDSM4(al,  cx.aLoB + cx.aOff + d);
            LDSM4(b0h, cx.bHiB + cx.bOff + d);
            LDSM4(b1h, cx.bHiB + cx.bOff + cx.P16 + d);
            LDSM4(b0l, cx.bLoB + cx.bOff + d);
            LDSM4(b1l, cx.bLoB + cx.bOff + cx.P16 + d);

            mma_bf16(acc[0][0], ah, &b0h[0]);
            mma_bf16(acc[0][1], ah, &b0h[2]);
            mma_bf16(acc[0][2], ah, &b1h[0]);
            mma_bf16(acc[0][3], ah, &b1h[2]);
            mma_bf16(acc[1][0], ah, &b0l[0]);
            mma_bf16(acc[1][1], ah, &b0l[2]);
            mma_bf16(acc[1][2], ah, &b1l[0]);
            mma_bf16(acc[1][3], ah, &b1l[2]);
            mma_bf16(acc[2][0], al, &b0h[0]);
            mma_bf16(acc[2][1], al, &b0h[2]);
            mma_bf16(acc[2][2], al, &b1h[0]);
            mma_bf16(acc[2][3], al, &b1h[2]);
        }
        __syncthreads();
    }
}

__device__ __forceinline__ GemmCtx make_ctx(bf16* dyn, int tid, int wm, int wn)
{
    GemmCtx cx;
    const int lane = tid & 31;
    cx.lrow = tid >> 2;
    cx.ck   = (tid & 3) * 8;
    cx.ldOff = (uint32_t)(cx.lrow * SKB + cx.ck) * 2;
    cx.aHiB = (uint32_t)__cvta_generic_to_shared(dyn);
    cx.aLoB = (uint32_t)__cvta_generic_to_shared(dyn + 2 * BUFE);
    cx.bHiB = (uint32_t)__cvta_generic_to_shared(dyn + 4 * BUFE);
    cx.bLoB = (uint32_t)__cvta_generic_to_shared(dyn + 6 * BUFE);
    const int rowA = wm + (lane & 7) + ((lane >> 3) & 1) * 8;
    const int colA = (lane >> 4) * 8;
    cx.aOff = (uint32_t)(rowA * SKB + colA) * 2;
    const int mB   = lane >> 3;
    const int rowB = wn + (mB >> 1) * 8 + (lane & 7);
    const int colB = (mB & 1) * 8;
    cx.bOff = (uint32_t)(rowB * SKB + colB) * 2;
    cx.P16  = (uint32_t)(16 * SKB) * 2;
    return cx;
}

// ---------------- head GEMM (z = 3 heads, relu+split epilogue) ---------------
__global__ __launch_bounds__(256)
void gemm_heads(const bf16* __restrict__ Ah0, const bf16* __restrict__ Ah1,
                const bf16* __restrict__ Ah2,
                const bf16* __restrict__ Al0, const bf16* __restrict__ Al1,
                const bf16* __restrict__ Al2,
                const bf16* __restrict__ Bh0, const bf16* __restrict__ Bh1,
                const bf16* __restrict__ Bh2,
                const bf16* __restrict__ Bl0, const bf16* __restrict__ Bl1,
                const bf16* __restrict__ Bl2,
                bf16* __restrict__ Ch0, bf16* __restrict__ Ch1,
                bf16* __restrict__ Ch2,
                bf16* __restrict__ Cl0, bf16* __restrict__ Cl1,
                bf16* __restrict__ Cl2,
                int M, int N, int K)
{
    const int bz = blockIdx.z;
    const bf16* __restrict__ Ah = (bz == 0) ? Ah0 : ((bz == 1) ? Ah1 : Ah2);
    const bf16* __restrict__ Al = (bz == 0) ? Al0 : ((bz == 1) ? Al1 : Al2);
    const bf16* __restrict__ Bh = (bz == 0) ? Bh0 : ((bz == 1) ? Bh1 : Bh2);
    const bf16* __restrict__ Bl = (bz == 0) ? Bl0 : ((bz == 1) ? Bl1 : Bl2);
    bf16* __restrict__ Ch       = (bz == 0) ? Ch0 : ((bz == 1) ? Ch1 : Ch2);
    bf16* __restrict__ Cl       = (bz == 0) ? Cl0 : ((bz == 1) ? Cl1 : Cl2);

    extern __shared__ __align__(16) bf16 dyn[];
    const int tid  = threadIdx.x;
    const int warp = tid >> 5;
    const int lane = tid & 31;
    const int g    = lane >> 2;
    const int tg   = lane & 3;
    const int m0 = blockIdx.y * 64;
    const int n0 = blockIdx.x * 64;
    const int wm = (warp >> 1) * 16;
    const int wn = (warp & 1) * 32;

    GemmCtx cx = make_ctx(dyn, tid, wm, wn);

    float acc[3][4][4];
#pragma unroll
    for (int ps = 0; ps < 3; ps++)
#pragma unroll
        for (int nt = 0; nt < 4; nt++)
#pragma unroll
            for (int i = 0; i < 4; i++) acc[ps][nt][i] = 0.0f;

    gemm_mainloop(Ah, Al, Bh, Bl, m0, n0, K, 0, K >> 5, cx, acc);

    const int r0 = m0 + wm + g;
    const int r1 = r0 + 8;
#pragma unroll
    for (int nt = 0; nt < 4; nt++) {
        const int col = n0 + wn + nt * 8 + 2 * tg;
        float s0 = fmaxf(acc[0][nt][0] + acc[1][nt][0] + acc[2][nt][0], 0.0f);
        float s1 = fmaxf(acc[0][nt][1] + acc[1][nt][1] + acc[2][nt][1], 0.0f);
        float s2 = fmaxf(acc[0][nt][2] + acc[1][nt][2] + acc[2][nt][2], 0.0f);
        float s3 = fmaxf(acc[0][nt][3] + acc[1][nt][3] + acc[2][nt][3], 0.0f);
        bf16 h0, l0, h1_, l1, h2, l2, h3, l3;
        split_bf16(s0, h0, l0); split_bf16(s1, h1_, l1);
        split_bf16(s2, h2, l2); split_bf16(s3, h3, l3);
        *(bf162*)&Ch[(size_t)r0 * N + col] = bf162(h0, h1_);
        *(bf162*)&Cl[(size_t)r0 * N + col] = bf162(l0, l1);
        *(bf162*)&Ch[(size_t)r1 * N + col] = bf162(h2, h3);
        *(bf162*)&Cl[(size_t)r1 * N + col] = bf162(l2, l3);
    }
}

// ---------------- split-K GEMM (z selects K-slice + partial buffer) ----------
__global__ __launch_bounds__(256)
void gemm_splitk(const bf16* __restrict__ Ah, const bf16* __restrict__ Al,
                 const bf16* __restrict__ Bh, const bf16* __restrict__ Bl,
                 float* __restrict__ P0, float* __restrict__ P1,
                 float* __restrict__ P2, float* __restrict__ P3,
                 int M, int N, int K, int Ksplit)
{
    const int bz = blockIdx.z;
    float* __restrict__ P = (bz == 0) ? P0 : ((bz == 1) ? P1 : ((bz == 2) ? P2 : P3));
    const int kbase = bz * Ksplit;

    extern __shared__ __align__(16) bf16 dyn[];
    const int tid  = threadIdx.x;
    const int warp = tid >> 5;
    const int lane = tid & 31;
    const int g    = lane >> 2;
    const int tg   = lane & 3;
    const int m0 = blockIdx.y * 64;
    const int n0 = blockIdx.x * 64;
    const int wm = (warp >> 1) * 16;
    const int wn = (warp & 1) * 32;

    GemmCtx cx = make_ctx(dyn, tid, wm, wn);

    float acc[3][4][4];
#pragma unroll
    for (int ps = 0; ps < 3; ps++)
#pragma unroll
        for (int nt = 0; nt < 4; nt++)
#pragma unroll
            for (int i = 0; i < 4; i++) acc[ps][nt][i] = 0.0f;

    gemm_mainloop(Ah, Al, Bh, Bl, m0, n0, K, kbase, Ksplit >> 5, cx, acc);

    const int r0 = m0 + wm + g;
    const int r1 = r0 + 8;
#pragma unroll
    for (int nt = 0; nt < 4; nt++) {
        const int col = n0 + wn + nt * 8 + 2 * tg;
        const float s0 = acc[0][nt][0] + acc[1][nt][0] + acc[2][nt][0];
        const float s1 = acc[0][nt][1] + acc[1][nt][1] + acc[2][nt][1];
        const float s2 = acc[0][nt][2] + acc[1][nt][2] + acc[2][nt][2];
        const float s3 = acc[0][nt][3] + acc[1][nt][3] + acc[2][nt][3];
        *(float2*)&P[(size_t)r0 * N + col] = make_float2(s0, s1);
        *(float2*)&P[(size_t)r1 * N + col] = make_float2(s2, s3);
    }
}

// ---------------- fused head-final projections -----------------------------
__global__ void head_final(const bf16* __restrict__ c2h, const bf16* __restrict__ c2l,
                           const bf16* __restrict__ i2h, const bf16* __restrict__ i2l,
                           const bf16* __restrict__ r2h, const bf16* __restrict__ r2l,
                           const float* __restrict__ wc, const float* __restrict__ bc,
                           const float* __restrict__ wi, const float* __restrict__ bi,
                           const float* __restrict__ wr, const float* __restrict__ br,
                           float* __restrict__ out, int N)
{
    const int warp = (blockIdx.x * blockDim.x + threadIdx.x) >> 5;
    const int lane = threadIdx.x & 31;
    if (warp >= N) return;

    float sc = 0.0f, si = 0.0f;
    float sr[7];
#pragma unroll
    for (int j = 0; j < 7; j++) sr[j] = 0.0f;

    const size_t base = (size_t)warp * DD;

#pragma unroll
    for (int kk = 0; kk < DD / 32; kk++) {
        const int k = lane + kk * 32;
        const float vc = __bfloat162float(c2h[base + k]) + __bfloat162float(c2l[base + k]);
        const float vi = __bfloat162float(i2h[base + k]) + __bfloat162float(i2l[base + k]);
        const float vr = __bfloat162float(r2h[base + k]) + __bfloat162float(r2l[base + k]);
        sc += vc * wc[k];
        si += vi * wi[k];
#pragma unroll
        for (int j = 0; j < 7; j++) sr[j] += vr * wr[j * DD + k];
    }

#pragma unroll
    for (int off = 16; off > 0; off >>= 1) {
        sc += __shfl_down_sync(0xffffffffu, sc, off);
        si += __shfl_down_sync(0xffffffffu, si, off);
#pragma unroll
        for (int j = 0; j < 7; j++) sr[j] += __shfl_down_sync(0xffffffffu, sr[j], off);
    }

    if (lane == 0) {
        out[warp]     = sc + bc[0];
        out[N + warp] = si + bi[0];
#pragma unroll
        for (int j = 0; j < 7; j++)
            out[2 * N + warp * 7 + j] = sr[j] + br[j];
    }
}

// ---------------- launch ----------------------------------------------------
extern "C" void kernel_launch(void* const* d_in, const int* in_sizes, int n_in,
                              void* d_out, int out_size)
{
    const float* fm    = (const float*)d_in[0];
    const float* boxes = (const float*)d_in[1];
    const int*   bidx  = (const int*)  d_in[2];
    const float* w_sh1 = (const float*)d_in[3];
    const float* w_sh2 = (const float*)d_in[4];
    const float* w_c1  = (const float*)d_in[5];
    const float* w_c2  = (const float*)d_in[6];
    const float* w_c3  = (const float*)d_in[7];
    const float* b_c3  = (const float*)d_in[8];
    const float* w_i1  = (const float*)d_in[9];
    const float* w_i2  = (const float*)d_in[10];
    const float* w_i3  = (const float*)d_in[11];
    const float* b_i3  = (const float*)d_in[12];
    const float* w_r1  = (const float*)d_in[13];
    const float* w_r2  = (const float*)d_in[14];
    const float* w_r3  = (const float*)d_in[15];
    const float* b_r3  = (const float*)d_in[16];
    float* out = (float*)d_out;

    const int N = in_sizes[2];

    float *pfmt, *pp0, *pp1, *pp2, *pp3;
    cudaGetSymbolAddress((void**)&pfmt, g_fmt);
    cudaGetSymbolAddress((void**)&pp0,  g_p0);
    cudaGetSymbolAddress((void**)&pp1,  g_p1);
    cudaGetSymbolAddress((void**)&pp2,  g_p2);
    cudaGetSymbolAddress((void**)&pp3,  g_p3);

#define SYM(p, s) bf16* p; cudaGetSymbolAddress((void**)&p, s)
    SYM(pxhi, g_xhi);   SYM(pxlo, g_xlo);
    SYM(pw1h, g_w1hi);  SYM(pw1l, g_w1lo);
    SYM(pw2h, g_w2hi);  SYM(pw2l, g_w2lo);
    SYM(pwc1h, g_wc1hi); SYM(pwc1l, g_wc1lo);
    SYM(pwi1h, g_wi1hi); SYM(pwi1l, g_wi1lo);
    SYM(pwr1h, g_wr1hi); SYM(pwr1l, g_wr1lo);
    SYM(pwc2h, g_wc2hi); SYM(pwc2l, g_wc2lo);
    SYM(pwi2h, g_wi2hi); SYM(pwi2l, g_wi2lo);
    SYM(pwr2h, g_wr2hi); SYM(pwr2l, g_wr2lo);
    SYM(ph1h, g_h1hi);  SYM(ph1l, g_h1lo);
    SYM(pshh, g_shhi);  SYM(pshl, g_shlo);
    SYM(pt1ch, g_t1chi); SYM(pt1cl, g_t1clo);
    SYM(pt1ih, g_t1ihi); SYM(pt1il, g_t1ilo);
    SYM(pt1rh, g_t1rhi); SYM(pt1rl, g_t1rlo);
    SYM(pc2h, g_c2hi);  SYM(pc2l, g_c2lo);
    SYM(pi2h, g_i2hi);  SYM(pi2l, g_i2lo);
    SYM(pr2h, g_r2hi);  SYM(pr2l, g_r2lo);
#undef SYM

    cudaFuncSetAttribute(gemm_heads,
                         cudaFuncAttributeMaxDynamicSharedMemorySize, SMEM_GEMM);
    cudaFuncSetAttribute(gemm_splitk,
                         cudaFuncAttributeMaxDynamicSharedMemorySize, SMEM_GEMM);

    // 0a) merged weight splits
    {
        const int total = DD * FDIM + 7 * DD * DD;
        wsplit_all<<<total / 1024, 256>>>(
            w_sh1, w_sh2, w_c1, w_i1, w_r1, w_c2, w_i2, w_r2,
            pw1h, pw1l, pw2h, pw2l, pwc1h, pwc1l, pwi1h, pwi1l,
            pwr1h, pwr1l, pwc2h, pwc2l, pwi2h, pwi2l, pwr2h, pwr2l);
    }

    // 0b) NCHW -> NHWC
    {
        dim3 grid(HH * WW / 128, CC / 64, BB);
        transpose_kernel<<<grid, 256>>>(fm, pfmt);
    }

    // 1) RoIAlignRotated -> x hi/lo [N, 2304]
    roi_kernel<<<N, 64>>>(pfmt, boxes, bidx, pxhi, pxlo);

    const int combineBlocks = N * DD / 1024;

    // 2) trunk GEMM 1 (split-K = 4 x 576) + combine
    {
        dim3 grid(DD / 64, N / 64, 4);
        gemm_splitk<<<grid, 256, SMEM_GEMM>>>(pxhi, pxlo, pw1h, pw1l,
                                              pp0, pp1, pp2, pp3,
                                              N, DD, FDIM, FDIM / 4);
        combine_relu_split<<<combineBlocks, 256>>>(pp0, pp1, pp2, pp3,
                                                   ph1h, ph1l, 1);
    }

    // 3) trunk GEMM 2 (split-K = 2 x 128) + combine
    {
        dim3 grid(DD / 64, N / 64, 2);
        gemm_splitk<<<grid, 256, SMEM_GEMM>>>(ph1h, ph1l, pw2h, pw2l,
                                              pp0, pp1, pp2, pp3,
                                              N, DD, DD, DD / 2);
        combine_relu_split<<<combineBlocks, 256>>>(pp0, pp1, pp2, pp3,
                                                   pshh, pshl, 0);
    }

    // 4) heads, batched over z=3
    dim3 grid3(DD / 64, N / 64, 3);
    gemm_heads<<<grid3, 256, SMEM_GEMM>>>(
        pshh, pshh, pshh, pshl, pshl, pshl,
        pwc1h, pwi1h, pwr1h, pwc1l, pwi1l, pwr1l,
        pt1ch, pt1ih, pt1rh, pt1cl, pt1il, pt1rl,
        N, DD, DD);
    gemm_heads<<<grid3, 256, SMEM_GEMM>>>(
        pt1ch, pt1ih, pt1rh, pt1cl, pt1il, pt1rl,
        pwc2h, pwi2h, pwr2h, pwc2l, pwi2l, pwr2l,
        pc2h, pi2h, pr2h, pc2l, pi2l, pr2l,
        N, DD, DD);

    // 5) final projections
    {
        const int threads = 256;
        const int blocks = (N * 32 + threads - 1) / threads;
        head_final<<<blocks, threads>>>(pc2h, pc2l, pi2h, pi2l, pr2h, pr2l,
                                        w_c3, b_c3, w_i3, b_i3, w_r3, b_r3,
                                        out, N);
    }
}

// round 10
// speedup vs baseline: 1.0821x; 1.0821x over previous
#include <cuda_runtime.h>
#include <cuda_bf16.h>
#include <cstdint>

#define BB 4
#define CC 256
#define HH 256
#define WW 256
#define NROI_MAX 2048
#define FDIM 2304
#define DD 256

typedef __nv_bfloat16 bf16;
typedef __nv_bfloat162 bf162;

// ---------------- scratch ----------------------------------------------------
__device__ float g_fmt[BB * HH * WW * CC];

__device__ bf16 g_xhi[NROI_MAX * FDIM];
__device__ bf16 g_xlo[NROI_MAX * FDIM];

__device__ bf16 g_w1hi[DD * FDIM], g_w1lo[DD * FDIM];
__device__ bf16 g_w2hi[DD * DD],   g_w2lo[DD * DD];
__device__ bf16 g_wc1hi[DD * DD],  g_wc1lo[DD * DD];
__device__ bf16 g_wi1hi[DD * DD],  g_wi1lo[DD * DD];
__device__ bf16 g_wr1hi[DD * DD],  g_wr1lo[DD * DD];
__device__ bf16 g_wc2hi[DD * DD],  g_wc2lo[DD * DD];
__device__ bf16 g_wi2hi[DD * DD],  g_wi2lo[DD * DD];
__device__ bf16 g_wr2hi[DD * DD],  g_wr2lo[DD * DD];

__device__ float g_p0[NROI_MAX * DD];
__device__ float g_p1[NROI_MAX * DD];
__device__ float g_p2[NROI_MAX * DD];
__device__ float g_p3[NROI_MAX * DD];

__device__ bf16 g_h1hi[NROI_MAX * DD],  g_h1lo[NROI_MAX * DD];
__device__ bf16 g_shhi[NROI_MAX * DD],  g_shlo[NROI_MAX * DD];
__device__ bf16 g_t1chi[NROI_MAX * DD], g_t1clo[NROI_MAX * DD];
__device__ bf16 g_t1ihi[NROI_MAX * DD], g_t1ilo[NROI_MAX * DD];
__device__ bf16 g_t1rhi[NROI_MAX * DD], g_t1rlo[NROI_MAX * DD];
__device__ bf16 g_c2hi[NROI_MAX * DD],  g_c2lo[NROI_MAX * DD];
__device__ bf16 g_i2hi[NROI_MAX * DD],  g_i2lo[NROI_MAX * DD];
__device__ bf16 g_r2hi[NROI_MAX * DD],  g_r2lo[NROI_MAX * DD];

__device__ __forceinline__ void split_bf16(float f, bf16& h, bf16& l)
{
    h = __float2bfloat16(f);
    l = __float2bfloat16(f - __bfloat162float(h));
}

// ---------------- NCHW -> NHWC transpose (64c x 64s, R8 version) ------------
__global__ __launch_bounds__(256)
void transpose_kernel(const float* __restrict__ fm, float* __restrict__ fmt)
{
    __shared__ float tile[64][65];

    const int b  = blockIdx.z;
    const int s0 = blockIdx.x * 64;
    const int c0 = blockIdx.y * 64;
    const int t  = threadIdx.x;

#pragma unroll
    for (int l = 0; l < 4; l++) {
        const int slot = t + l * 256;
        const int ci = slot >> 4;
        const int s4 = (slot & 15) * 4;
        const float4 v = *(const float4*)(fm +
            ((size_t)b * CC + (c0 + ci)) * (size_t)(HH * WW) + s0 + s4);
        tile[ci][s4 + 0] = v.x;
        tile[ci][s4 + 1] = v.y;
        tile[ci][s4 + 2] = v.z;
        tile[ci][s4 + 3] = v.w;
    }
    __syncthreads();

#pragma unroll
    for (int l = 0; l < 4; l++) {
        const int slot = t + l * 256;
        const int si = slot >> 4;
        const int c4 = (slot & 15) * 4;
        float4 v;
        v.x = tile[c4 + 0][si];
        v.y = tile[c4 + 1][si];
        v.z = tile[c4 + 2][si];
        v.w = tile[c4 + 3][si];
        *(float4*)(fmt + ((size_t)b * (HH * WW) + s0 + si) * (size_t)CC + c0 + c4) = v;
    }
}

// ---------------- RoIAlignRotated (NHWC gather, writes hi/lo bf16) ----------
__global__ __launch_bounds__(64)
void roi_kernel(const float* __restrict__ fmt,
                const float* __restrict__ boxes,
                const int*   __restrict__ bidx,
                bf16* __restrict__ xhi, bf16* __restrict__ xlo)
{
    const int n = blockIdx.x;
    const int t = threadIdx.x;

    __shared__ int   s_o[36][4];
    __shared__ float s_w[36][4];

    if (t < 36) {
        const float gw = (float)(102.4 / 256.0);
        const float bx  = boxes[n*7 + 0];
        const float by  = boxes[n*7 + 1];
        const float rh  = boxes[n*7 + 4] / gw;
        const float rw  = boxes[n*7 + 5] / gw;
        const float ang = boxes[n*7 + 6];

        const float cx = (bx + 51.2f) / gw - 0.5f;
        const float cy = (by + 51.2f) / gw - 0.5f;
        const float ct = cosf(-ang);
        const float st = sinf(-ang);
        const float bin_h = rh / 3.0f;
        const float bin_w = rw / 3.0f;

        const int p  = t;
        const int ph = p / 12;
        const int pw = (p / 4) % 3;
        const int sy = (p >> 1) & 1;
        const int sx = p & 1;

        const float yy = -rh * 0.5f + ((float)ph + ((float)sy + 0.5f) * 0.5f) * bin_h;
        const float xx = -rw * 0.5f + ((float)pw + ((float)sx + 0.5f) * 0.5f) * bin_w;

        float y = yy * ct - xx * st + cy;
        float x = yy * st + xx * ct + cx;

        const bool valid = (y > -1.0f) && (y < (float)HH) && (x > -1.0f) && (x < (float)WW);

        y = fminf(fmaxf(y, 0.0f), (float)(HH - 1));
        x = fminf(fmaxf(x, 0.0f), (float)(WW - 1));

        int y0 = min((int)floorf(y), HH - 1);
        int x0 = min((int)floorf(x), WW - 1);
        int y1 = min(y0 + 1, HH - 1);
        int x1 = min(x0 + 1, WW - 1);

        const float ly = y - (float)y0;
        const float lx = x - (float)x0;
        const float hy = 1.0f - ly;
        const float hx = 1.0f - lx;
        const float v  = valid ? 1.0f : 0.0f;

        s_o[p][0] = (y0 * WW + x0) * CC;
        s_o[p][1] = (y0 * WW + x1) * CC;
        s_o[p][2] = (y1 * WW + x0) * CC;
        s_o[p][3] = (y1 * WW + x1) * CC;
        s_w[p][0] = hy * hx * v;
        s_w[p][1] = hy * lx * v;
        s_w[p][2] = ly * hx * v;
        s_w[p][3] = ly * lx * v;
    }
    __syncthreads();

    const int b = bidx[n];
    const float* __restrict__ base = fmt + (size_t)b * (HH * WW) * CC + t * 4;

    float4 acc[9];
#pragma unroll
    for (int i = 0; i < 9; i++) acc[i] = make_float4(0.f, 0.f, 0.f, 0.f);

#pragma unroll
    for (int p = 0; p < 36; p++) {
        const float4 v0 = *(const float4*)(base + s_o[p][0]);
        const float4 v1 = *(const float4*)(base + s_o[p][1]);
        const float4 v2 = *(const float4*)(base + s_o[p][2]);
        const float4 v3 = *(const float4*)(base + s_o[p][3]);
        const float w0 = s_w[p][0], w1 = s_w[p][1], w2 = s_w[p][2], w3 = s_w[p][3];
        float4& a = acc[p >> 2];
        a.x += w0 * v0.x + w1 * v1.x + w2 * v2.x + w3 * v3.x;
        a.y += w0 * v0.y + w1 * v1.y + w2 * v2.y + w3 * v3.y;
        a.z += w0 * v0.z + w1 * v1.z + w2 * v2.z + w3 * v3.z;
        a.w += w0 * v0.w + w1 * v1.w + w2 * v2.w + w3 * v3.w;
    }

    const size_t ob = (size_t)n * FDIM + t * 4;
#pragma unroll
    for (int i = 0; i < 9; i++) {
        float r[4] = {acc[i].x * 0.25f, acc[i].y * 0.25f,
                      acc[i].z * 0.25f, acc[i].w * 0.25f};
        bf16 h[4], l[4];
#pragma unroll
        for (int j = 0; j < 4; j++) split_bf16(r[j], h[j], l[j]);
        *(bf162*)(xhi + ob + i * CC)     = bf162(h[0], h[1]);
        *(bf162*)(xhi + ob + i * CC + 2) = bf162(h[2], h[3]);
        *(bf162*)(xlo + ob + i * CC)     = bf162(l[0], l[1]);
        *(bf162*)(xlo + ob + i * CC + 2) = bf162(l[2], l[3]);
    }
}

// ---------------- merged weight split ---------------------------------------
__global__ __launch_bounds__(256)
void wsplit_all(const float* __restrict__ w1,
                const float* __restrict__ s0w, const float* __restrict__ s1w,
                const float* __restrict__ s2w, const float* __restrict__ s3w,
                const float* __restrict__ s4w, const float* __restrict__ s5w,
                const float* __restrict__ s6w,
                bf16* __restrict__ w1h, bf16* __restrict__ w1l,
                bf16* __restrict__ s0h, bf16* __restrict__ s0l,
                bf16* __restrict__ s1h, bf16* __restrict__ s1l,
                bf16* __restrict__ s2h, bf16* __restrict__ s2l,
                bf16* __restrict__ s3h, bf16* __restrict__ s3l,
                bf16* __restrict__ s4h, bf16* __restrict__ s4l,
                bf16* __restrict__ s5h, bf16* __restrict__ s5l,
                bf16* __restrict__ s6h, bf16* __restrict__ s6l)
{
    const int idx4 = (blockIdx.x * 256 + threadIdx.x) * 4;
    const int W1N = DD * FDIM;

    const float* w; bf16* h; bf16* l; int off;
    if (idx4 < W1N) {
        w = w1; h = w1h; l = w1l; off = idx4;
    } else {
        const int r = idx4 - W1N;
        const int seg = r >> 16;
        off = r & 65535;
        w = (seg == 0) ? s0w : (seg == 1) ? s1w : (seg == 2) ? s2w :
            (seg == 3) ? s3w : (seg == 4) ? s4w : (seg == 5) ? s5w : s6w;
        h = (seg == 0) ? s0h : (seg == 1) ? s1h : (seg == 2) ? s2h :
            (seg == 3) ? s3h : (seg == 4) ? s4h : (seg == 5) ? s5h : s6h;
        l = (seg == 0) ? s0l : (seg == 1) ? s1l : (seg == 2) ? s2l :
            (seg == 3) ? s3l : (seg == 4) ? s4l : (seg == 5) ? s5l : s6l;
    }

    const float4 v = *(const float4*)(w + off);
    bf16 h0, l0, h1, l1, h2, l2, h3, l3;
    split_bf16(v.x, h0, l0); split_bf16(v.y, h1, l1);
    split_bf16(v.z, h2, l2); split_bf16(v.w, h3, l3);
    *(bf162*)(h + off)     = bf162(h0, h1);
    *(bf162*)(h + off + 2) = bf162(h2, h3);
    *(bf162*)(l + off)     = bf162(l0, l1);
    *(bf162*)(l + off + 2) = bf162(l2, l3);
}

// ---------------- combine split-K partials: relu(sum Pi) -> hi/lo -----------
__global__ __launch_bounds__(256)
void combine_relu_split(const float* __restrict__ P0, const float* __restrict__ P1,
                        const float* __restrict__ P2, const float* __restrict__ P3,
                        bf16* __restrict__ Oh, bf16* __restrict__ Ol, int four)
{
    const int off = (blockIdx.x * 256 + threadIdx.x) * 4;
    const float4 a = *(const float4*)(P0 + off);
    const float4 b = *(const float4*)(P1 + off);
    float r[4] = {a.x + b.x, a.y + b.y, a.z + b.z, a.w + b.w};
    if (four) {
        const float4 c = *(const float4*)(P2 + off);
        const float4 d = *(const float4*)(P3 + off);
        r[0] += c.x + d.x; r[1] += c.y + d.y;
        r[2] += c.z + d.z; r[3] += c.w + d.w;
    }
    bf16 h[4], l[4];
#pragma unroll
    for (int j = 0; j < 4; j++) {
        r[j] = fmaxf(r[j], 0.0f);
        split_bf16(r[j], h[j], l[j]);
    }
    *(bf162*)(Oh + off)     = bf162(h[0], h[1]);
    *(bf162*)(Oh + off + 2) = bf162(h[2], h[3]);
    *(bf162*)(Ol + off)     = bf162(l[0], l[1]);
    *(bf162*)(Ol + off + 2) = bf162(l[2], l[3]);
}

// ---------------- GEMM common ------------------------------------------------
__device__ __forceinline__ void mma_bf16(float* d, const uint32_t* a, const uint32_t* b)
{
    asm volatile(
        "mma.sync.aligned.m16n8k16.row.col.f32.bf16.bf16.f32 "
        "{%0,%1,%2,%3}, {%4,%5,%6,%7}, {%8,%9}, {%0,%1,%2,%3};\n"
        : "+f"(d[0]), "+f"(d[1]), "+f"(d[2]), "+f"(d[3])
        : "r"(a[0]), "r"(a[1]), "r"(a[2]), "r"(a[3]), "r"(b[0]), "r"(b[1]));
}

__device__ __forceinline__ void cp_async16(uint32_t smem_addr, const void* gptr)
{
    asm volatile("cp.async.cg.shared.global [%0], [%1], 16;\n"
                 :: "r"(smem_addr), "l"(gptr));
}

#define LDSM4(r, addr) \
    asm volatile("ldmatrix.sync.aligned.m8n8.x4.shared.b16 {%0,%1,%2,%3}, [%4];" \
                 : "=r"((r)[0]), "=r"((r)[1]), "=r"((r)[2]), "=r"((r)[3]) \
                 : "r"(addr))

#define SKB 40
#define BUFE (64 * SKB)                 // elems per array per stage
#define BUFB (BUFE * 2)                 // bytes per array per stage
#define STAGES 3
#define SMEM_GEMM (STAGES * 4 * BUFB)   // 61440 B

struct GemmCtx {
    uint32_t aHiB, aLoB, bHiB, bLoB, ldOff, aOff, bOff, P16;
    int lrow, ck;
};

// 3-stage pipeline, ONE barrier per BK-iteration (cutlass ordering).
__device__ __forceinline__ void gemm_mainloop(
    const bf16* __restrict__ Ah, const bf16* __restrict__ Al,
    const bf16* __restrict__ Bh, const bf16* __restrict__ Bl,
    int m0, int n0, int K, int kbase, int T,
    const GemmCtx& cx, float acc[3][4][4])
{
    const int lrow = cx.lrow, ck = cx.ck;

    // prologue: stages 0..S-2
#pragma unroll
    for (int s = 0; s < STAGES - 1; s++) {
        const uint32_t so = (uint32_t)s * BUFB;
        const int ko = kbase + (s << 5);
        const size_t ka = (size_t)(m0 + lrow) * K + ko + ck;
        const size_t kb = (size_t)(n0 + lrow) * K + ko + ck;
        cp_async16(cx.aHiB + so + cx.ldOff, Ah + ka);
        cp_async16(cx.aLoB + so + cx.ldOff, Al + ka);
        cp_async16(cx.bHiB + so + cx.ldOff, Bh + kb);
        cp_async16(cx.bLoB + so + cx.ldOff, Bl + kb);
        asm volatile("cp.async.commit_group;\n");
    }

    int cbuf = 0;               // compute stage
    int pbuf = STAGES - 1;      // prefetch stage
    for (int kt = 0; kt < T; kt++) {
        asm volatile("cp.async.wait_group %0;\n" :: "n"(STAGES - 2));
        __syncthreads();

        // prefetch kt + STAGES-1 (after barrier: all warps done with this buffer)
        if (kt + STAGES - 1 < T) {
            const uint32_t so = (uint32_t)pbuf * BUFB;
            const int ko = kbase + ((kt + STAGES - 1) << 5);
            const size_t ka = (size_t)(m0 + lrow) * K + ko + ck;
            const size_t kb = (size_t)(n0 + lrow) * K + ko + ck;
            cp_async16(cx.aHiB + so + cx.ldOff, Ah + ka);
            cp_async16(cx.aLoB + so + cx.ldOff, Al + ka);
            cp_async16(cx.bHiB + so + cx.ldOff, Bh + kb);
            cp_async16(cx.bLoB + so + cx.ldOff, Bl + kb);
        }
        asm volatile("cp.async.commit_group;\n");

        const uint32_t buf = (uint32_t)cbuf * BUFB;
#pragma unroll
        for (int ks = 0; ks < 32; ks += 16) {
            const uint32_t d = buf + (uint32_t)ks * 2;
            uint32_t ah[4], al[4], b0h[4], b1h[4], b0l[4], b1l[4];
            LDSM4(ah,  cx.aHiB + cx.aOff + d);
            LDSM4(al,  cx.aLoB + cx.aOff + d);
            LDSM4(b0h, cx.bHiB + cx.bOff + d);
            LDSM4(b1h, cx.bHiB + cx.bOff + cx.P16 + d);
            LDSM4(b0l, cx.bLoB + cx.bOff + d);
            LDSM4(b1l, cx.bLoB + cx.bOff + cx.P16 + d);

            mma_bf16(acc[0][0], ah, &b0h[0]);
            mma_bf16(acc[0][1], ah, &b0h[2]);
            mma_bf16(acc[0][2], ah, &b1h[0]);
            mma_bf16(acc[0][3], ah, &b1h[2]);
            mma_bf16(acc[1][0], ah, &b0l[0]);
            mma_bf16(acc[1][1], ah, &b0l[2]);
            mma_bf16(acc[1][2], ah, &b1l[0]);
            mma_bf16(acc[1][3], ah, &b1l[2]);
            mma_bf16(acc[2][0], al, &b0h[0]);
            mma_bf16(acc[2][1], al, &b0h[2]);
            mma_bf16(acc[2][2], al, &b1h[0]);
            mma_bf16(acc[2][3], al, &b1h[2]);
        }

        cbuf = (cbuf + 1 == STAGES) ? 0 : cbuf + 1;
        pbuf = (pbuf + 1 == STAGES) ? 0 : pbuf + 1;
    }
}

__device__ __forceinline__ GemmCtx make_ctx(bf16* dyn, int tid, int wm, int wn)
{
    GemmCtx cx;
    const int lane = tid & 31;
    cx.lrow = tid >> 2;
    cx.ck   = (tid & 3) * 8;
    cx.ldOff = (uint32_t)(cx.lrow * SKB + cx.ck) * 2;
    cx.aHiB = (uint32_t)__cvta_generic_to_shared(dyn);
    cx.aLoB = (uint32_t)__cvta_generic_to_shared(dyn + STAGES * BUFE);
    cx.bHiB = (uint32_t)__cvta_generic_to_shared(dyn + 2 * STAGES * BUFE);
    cx.bLoB = (uint32_t)__cvta_generic_to_shared(dyn + 3 * STAGES * BUFE);
    const int rowA = wm + (lane & 7) + ((lane >> 3) & 1) * 8;
    const int colA = (lane >> 4) * 8;
    cx.aOff = (uint32_t)(rowA * SKB + colA) * 2;
    const int mB   = lane >> 3;
    const int rowB = wn + (mB >> 1) * 8 + (lane & 7);
    const int colB = (mB & 1) * 8;
    cx.bOff = (uint32_t)(rowB * SKB + colB) * 2;
    cx.P16  = (uint32_t)(16 * SKB) * 2;
    return cx;
}

// ---------------- head GEMM (z = 3 heads, relu+split epilogue) ---------------
__global__ __launch_bounds__(256)
void gemm_heads(const bf16* __restrict__ Ah0, const bf16* __restrict__ Ah1,
                const bf16* __restrict__ Ah2,
                const bf16* __restrict__ Al0, const bf16* __restrict__ Al1,
                const bf16* __restrict__ Al2,
                const bf16* __restrict__ Bh0, const bf16* __restrict__ Bh1,
                const bf16* __restrict__ Bh2,
                const bf16* __restrict__ Bl0, const bf16* __restrict__ Bl1,
                const bf16* __restrict__ Bl2,
                bf16* __restrict__ Ch0, bf16* __restrict__ Ch1,
                bf16* __restrict__ Ch2,
                bf16* __restrict__ Cl0, bf16* __restrict__ Cl1,
                bf16* __restrict__ Cl2,
                int M, int N, int K)
{
    const int bz = blockIdx.z;
    const bf16* __restrict__ Ah = (bz == 0) ? Ah0 : ((bz == 1) ? Ah1 : Ah2);
    const bf16* __restrict__ Al = (bz == 0) ? Al0 : ((bz == 1) ? Al1 : Al2);
    const bf16* __restrict__ Bh = (bz == 0) ? Bh0 : ((bz == 1) ? Bh1 : Bh2);
    const bf16* __restrict__ Bl = (bz == 0) ? Bl0 : ((bz == 1) ? Bl1 : Bl2);
    bf16* __restrict__ Ch       = (bz == 0) ? Ch0 : ((bz == 1) ? Ch1 : Ch2);
    bf16* __restrict__ Cl       = (bz == 0) ? Cl0 : ((bz == 1) ? Cl1 : Cl2);

    extern __shared__ __align__(16) bf16 dyn[];
    const int tid  = threadIdx.x;
    const int warp = tid >> 5;
    const int lane = tid & 31;
    const int g    = lane >> 2;
    const int tg   = lane & 3;
    const int m0 = blockIdx.y * 64;
    const int n0 = blockIdx.x * 64;
    const int wm = (warp >> 1) * 16;
    const int wn = (warp & 1) * 32;

    GemmCtx cx = make_ctx(dyn, tid, wm, wn);

    float acc[3][4][4];
#pragma unroll
    for (int ps = 0; ps < 3; ps++)
#pragma unroll
        for (int nt = 0; nt < 4; nt++)
#pragma unroll
            for (int i = 0; i < 4; i++) acc[ps][nt][i] = 0.0f;

    gemm_mainloop(Ah, Al, Bh, Bl, m0, n0, K, 0, K >> 5, cx, acc);

    const int r0 = m0 + wm + g;
    const int r1 = r0 + 8;
#pragma unroll
    for (int nt = 0; nt < 4; nt++) {
        const int col = n0 + wn + nt * 8 + 2 * tg;
        float s0 = fmaxf(acc[0][nt][0] + acc[1][nt][0] + acc[2][nt][0], 0.0f);
        float s1 = fmaxf(acc[0][nt][1] + acc[1][nt][1] + acc[2][nt][1], 0.0f);
        float s2 = fmaxf(acc[0][nt][2] + acc[1][nt][2] + acc[2][nt][2], 0.0f);
        float s3 = fmaxf(acc[0][nt][3] + acc[1][nt][3] + acc[2][nt][3], 0.0f);
        bf16 h0, l0, h1_, l1, h2, l2, h3, l3;
        split_bf16(s0, h0, l0); split_bf16(s1, h1_, l1);
        split_bf16(s2, h2, l2); split_bf16(s3, h3, l3);
        *(bf162*)&Ch[(size_t)r0 * N + col] = bf162(h0, h1_);
        *(bf162*)&Cl[(size_t)r0 * N + col] = bf162(l0, l1);
        *(bf162*)&Ch[(size_t)r1 * N + col] = bf162(h2, h3);
        *(bf162*)&Cl[(size_t)r1 * N + col] = bf162(l2, l3);
    }
}

// ---------------- split-K GEMM (z selects K-slice + partial buffer) ----------
__global__ __launch_bounds__(256)
void gemm_splitk(const bf16* __restrict__ Ah, const bf16* __restrict__ Al,
                 const bf16* __restrict__ Bh, const bf16* __restrict__ Bl,
                 float* __restrict__ P0, float* __restrict__ P1,
                 float* __restrict__ P2, float* __restrict__ P3,
                 int M, int N, int K, int Ksplit)
{
    const int bz = blockIdx.z;
    float* __restrict__ P = (bz == 0) ? P0 : ((bz == 1) ? P1 : ((bz == 2) ? P2 : P3));
    const int kbase = bz * Ksplit;

    extern __shared__ __align__(16) bf16 dyn[];
    const int tid  = threadIdx.x;
    const int warp = tid >> 5;
    const int lane = tid & 31;
    const int g    = lane >> 2;
    const int tg   = lane & 3;
    const int m0 = blockIdx.y * 64;
    const int n0 = blockIdx.x * 64;
    const int wm = (warp >> 1) * 16;
    const int wn = (warp & 1) * 32;

    GemmCtx cx = make_ctx(dyn, tid, wm, wn);

    float acc[3][4][4];
#pragma unroll
    for (int ps = 0; ps < 3; ps++)
#pragma unroll
        for (int nt = 0; nt < 4; nt++)
#pragma unroll
            for (int i = 0; i < 4; i++) acc[ps][nt][i] = 0.0f;

    gemm_mainloop(Ah, Al, Bh, Bl, m0, n0, K, kbase, Ksplit >> 5, cx, acc);

    const int r0 = m0 + wm + g;
    const int r1 = r0 + 8;
#pragma unroll
    for (int nt = 0; nt < 4; nt++) {
        const int col = n0 + wn + nt * 8 + 2 * tg;
        const float s0 = acc[0][nt][0] + acc[1][nt][0] + acc[2][nt][0];
        const float s1 = acc[0][nt][1] + acc[1][nt][1] + acc[2][nt][1];
        const float s2 = acc[0][nt][2] + acc[1][nt][2] + acc[2][nt][2];
        const float s3 = acc[0][nt][3] + acc[1][nt][3] + acc[2][nt][3];
        *(float2*)&P[(size_t)r0 * N + col] = make_float2(s0, s1);
        *(float2*)&P[(size_t)r1 * N + col] = make_float2(s2, s3);
    }
}

// ---------------- fused head-final projections -----------------------------
__global__ void head_final(const bf16* __restrict__ c2h, const bf16* __restrict__ c2l,
                           const bf16* __restrict__ i2h, const bf16* __restrict__ i2l,
                           const bf16* __restrict__ r2h, const bf16* __restrict__ r2l,
                           const float* __restrict__ wc, const float* __restrict__ bc,
                           const float* __restrict__ wi, const float* __restrict__ bi,
                           const float* __restrict__ wr, const float* __restrict__ br,
                           float* __restrict__ out, int N)
{
    const int warp = (blockIdx.x * blockDim.x + threadIdx.x) >> 5;
    const int lane = threadIdx.x & 31;
    if (warp >= N) return;

    float sc = 0.0f, si = 0.0f;
    float sr[7];
#pragma unroll
    for (int j = 0; j < 7; j++) sr[j] = 0.0f;

    const size_t base = (size_t)warp * DD;

#pragma unroll
    for (int kk = 0; kk < DD / 32; kk++) {
        const int k = lane + kk * 32;
        const float vc = __bfloat162float(c2h[base + k]) + __bfloat162float(c2l[base + k]);
        const float vi = __bfloat162float(i2h[base + k]) + __bfloat162float(i2l[base + k]);
        const float vr = __bfloat162float(r2h[base + k]) + __bfloat162float(r2l[base + k]);
        sc += vc * wc[k];
        si += vi * wi[k];
#pragma unroll
        for (int j = 0; j < 7; j++) sr[j] += vr * wr[j * DD + k];
    }

#pragma unroll
    for (int off = 16; off > 0; off >>= 1) {
        sc += __shfl_down_sync(0xffffffffu, sc, off);
        si += __shfl_down_sync(0xffffffffu, si, off);
#pragma unroll
        for (int j = 0; j < 7; j++) sr[j] += __shfl_down_sync(0xffffffffu, sr[j], off);
    }

    if (lane == 0) {
        out[warp]     = sc + bc[0];
        out[N + warp] = si + bi[0];
#pragma unroll
        for (int j = 0; j < 7; j++)
            out[2 * N + warp * 7 + j] = sr[j] + br[j];
    }
}

// ---------------- launch ----------------------------------------------------
extern "C" void kernel_launch(void* const* d_in, const int* in_sizes, int n_in,
                              void* d_out, int out_size)
{
    const float* fm    = (const float*)d_in[0];
    const float* boxes = (const float*)d_in[1];
    const int*   bidx  = (const int*)  d_in[2];
    const float* w_sh1 = (const float*)d_in[3];
    const float* w_sh2 = (const float*)d_in[4];
    const float* w_c1  = (const float*)d_in[5];
    const float* w_c2  = (const float*)d_in[6];
    const float* w_c3  = (const float*)d_in[7];
    const float* b_c3  = (const float*)d_in[8];
    const float* w_i1  = (const float*)d_in[9];
    const float* w_i2  = (const float*)d_in[10];
    const float* w_i3  = (const float*)d_in[11];
    const float* b_i3  = (const float*)d_in[12];
    const float* w_r1  = (const float*)d_in[13];
    const float* w_r2  = (const float*)d_in[14];
    const float* w_r3  = (const float*)d_in[15];
    const float* b_r3  = (const float*)d_in[16];
    float* out = (float*)d_out;

    const int N = in_sizes[2];

    float *pfmt, *pp0, *pp1, *pp2, *pp3;
    cudaGetSymbolAddress((void**)&pfmt, g_fmt);
    cudaGetSymbolAddress((void**)&pp0,  g_p0);
    cudaGetSymbolAddress((void**)&pp1,  g_p1);
    cudaGetSymbolAddress((void**)&pp2,  g_p2);
    cudaGetSymbolAddress((void**)&pp3,  g_p3);

#define SYM(p, s) bf16* p; cudaGetSymbolAddress((void**)&p, s)
    SYM(pxhi, g_xhi);   SYM(pxlo, g_xlo);
    SYM(pw1h, g_w1hi);  SYM(pw1l, g_w1lo);
    SYM(pw2h, g_w2hi);  SYM(pw2l, g_w2lo);
    SYM(pwc1h, g_wc1hi); SYM(pwc1l, g_wc1lo);
    SYM(pwi1h, g_wi1hi); SYM(pwi1l, g_wi1lo);
    SYM(pwr1h, g_wr1hi); SYM(pwr1l, g_wr1lo);
    SYM(pwc2h, g_wc2hi); SYM(pwc2l, g_wc2lo);
    SYM(pwi2h, g_wi2hi); SYM(pwi2l, g_wi2lo);
    SYM(pwr2h, g_wr2hi); SYM(pwr2l, g_wr2lo);
    SYM(ph1h, g_h1hi);  SYM(ph1l, g_h1lo);
    SYM(pshh, g_shhi);  SYM(pshl, g_shlo);
    SYM(pt1ch, g_t1chi); SYM(pt1cl, g_t1clo);
    SYM(pt1ih, g_t1ihi); SYM(pt1il, g_t1ilo);
    SYM(pt1rh, g_t1rhi); SYM(pt1rl, g_t1rlo);
    SYM(pc2h, g_c2hi);  SYM(pc2l, g_c2lo);
    SYM(pi2h, g_i2hi);  SYM(pi2l, g_i2lo);
    SYM(pr2h, g_r2hi);  SYM(pr2l, g_r2lo);
#undef SYM

    cudaFuncSetAttribute(gemm_heads,
                         cudaFuncAttributeMaxDynamicSharedMemorySize, SMEM_GEMM);
    cudaFuncSetAttribute(gemm_splitk,
                         cudaFuncAttributeMaxDynamicSharedMemorySize, SMEM_GEMM);

    // 0a) merged weight splits
    {
        const int total = DD * FDIM + 7 * DD * DD;
        wsplit_all<<<total / 1024, 256>>>(
            w_sh1, w_sh2, w_c1, w_i1, w_r1, w_c2, w_i2, w_r2,
            pw1h, pw1l, pw2h, pw2l, pwc1h, pwc1l, pwi1h, pwi1l,
            pwr1h, pwr1l, pwc2h, pwc2l, pwi2h, pwi2l, pwr2h, pwr2l);
    }

    // 0b) NCHW -> NHWC
    {
        dim3 grid(HH * WW / 64, CC / 64, BB);
        transpose_kernel<<<grid, 256>>>(fm, pfmt);
    }

    // 1) RoIAlignRotated -> x hi/lo [N, 2304]
    roi_kernel<<<N, 64>>>(pfmt, boxes, bidx, pxhi, pxlo);

    const int combineBlocks = N * DD / 1024;

    // 2) trunk GEMM 1 (split-K = 4 x 576) + combine
    {
        dim3 grid(DD / 64, N / 64, 4);
        gemm_splitk<<<grid, 256, SMEM_GEMM>>>(pxhi, pxlo, pw1h, pw1l,
                                              pp0, pp1, pp2, pp3,
                                              N, DD, FDIM, FDIM / 4);
        combine_relu_split<<<combineBlocks, 256>>>(pp0, pp1, pp2, pp3,
                                                   ph1h, ph1l, 1);
    }

    // 3) trunk GEMM 2 (split-K = 2 x 128) + combine
    {
        dim3 grid(DD / 64, N / 64, 2);
        gemm_splitk<<<grid, 256, SMEM_GEMM>>>(ph1h, ph1l, pw2h, pw2l,
                                              pp0, pp1, pp2, pp3,
                                              N, DD, DD, DD / 2);
        combine_relu_split<<<combineBlocks, 256>>>(pp0, pp1, pp2, pp3,
                                                   pshh, pshl, 0);
    }

    // 4) heads, batched over z=3
    dim3 grid3(DD / 64, N / 64, 3);
    gemm_heads<<<grid3, 256, SMEM_GEMM>>>(
        pshh, pshh, pshh, pshl, pshl, pshl,
        pwc1h, pwi1h, pwr1h, pwc1l, pwi1l, pwr1l,
        pt1ch, pt1ih, pt1rh, pt1cl, pt1il, pt1rl,
        N, DD, DD);
    gemm_heads<<<grid3, 256, SMEM_GEMM>>>(
        pt1ch, pt1ih, pt1rh, pt1cl, pt1il, pt1rl,
        pwc2h, pwi2h, pwr2h, pwc2l, pwi2l, pwr2l,
        pc2h, pi2h, pr2h, pc2l, pi2l, pr2l,
        N, DD, DD);

    // 5) final projections
    {
        const int threads = 256;
        const int blocks = (N * 32 + threads - 1) / threads;
        head_final<<<blocks, threads>>>(pc2h, pc2l, pi2h, pi2l, pr2h, pr2l,
                                        w_c3, b_c3, w_i3, b_i3, w_r3, b_r3,
                                        out, N);
    }
}